// round 13
// baseline (speedup 1.0000x reference)
#include <cuda_runtime.h>
#include <cuda_bf16.h>
#include <cuda_fp16.h>
#include <cstdint>

#define BATCH 8
#define SEQ   2048
#define DM    1024
#define DH    64
#define NTOK  (BATCH * SEQ)
#define ITILES 16

// ---------------- device scratch ----------------
__device__ __half g_W[3 * DH * DM];                // [mat*64+c][k], fp16
__device__ __half g_Q[NTOK * DH];                  // Q fp16
__device__ __half g_K[NTOK * DH];                  // K fp16
__device__ float  g_Vt[BATCH * DH * SEQ];          // V fp32, [b][d][i]
__device__ __half g_Vf[BATCH * DH * SEQ];          // V' = diag(c) V, fp16, [b][d][i]
__device__ float g_psum[BATCH * ITILES * SEQ];

// ---------------- helpers ----------------
__device__ __forceinline__ uint32_t s_u32(const void* p) {
    uint32_t a;
    asm("{ .reg .u64 t; cvta.to.shared.u64 t, %1; cvt.u32.u64 %0, t; }" : "=r"(a) : "l"(p));
    return a;
}
#define LDSM4(r0, r1, r2, r3, addr) \
    asm volatile("ldmatrix.sync.aligned.m8n8.x4.shared.b16 {%0,%1,%2,%3}, [%4];" \
                 : "=r"(r0), "=r"(r1), "=r"(r2), "=r"(r3) : "r"(addr))
#define CPA16(dst, src) \
    asm volatile("cp.async.cg.shared.global [%0], [%1], 16;" :: "r"(dst), "l"(src))
#define CPA_COMMIT() asm volatile("cp.async.commit_group;" ::: "memory")
#define CPA_WAIT1()  asm volatile("cp.async.wait_group 1;" ::: "memory")
#define CPA_WAIT0()  asm volatile("cp.async.wait_group 0;" ::: "memory")

__device__ __forceinline__ void mma_f16(float* c, const uint32_t* a, const uint32_t* b) {
    asm volatile(
        "mma.sync.aligned.m16n8k16.row.col.f32.f16.f16.f32 "
        "{%0,%1,%2,%3}, {%4,%5,%6,%7}, {%8,%9}, {%0,%1,%2,%3};"
        : "+f"(c[0]), "+f"(c[1]), "+f"(c[2]), "+f"(c[3])
        : "r"(a[0]), "r"(a[1]), "r"(a[2]), "r"(a[3]), "r"(b[0]), "r"(b[1]));
}
__device__ __forceinline__ uint32_t pk2(unsigned short a, unsigned short b) {
    return (uint32_t)a | ((uint32_t)b << 16);
}
__device__ __forceinline__ unsigned short h16(float v) {
    return __half_as_ushort(__float2half(v));
}

// ---------------- W -> fp16 transpose ----------------
__global__ __launch_bounds__(256) void split_w_kernel(
    const float* __restrict__ Wq, const float* __restrict__ Wk, const float* __restrict__ Wv) {
    int mt = blockIdx.y;
    const float* W = (mt == 0) ? Wq : (mt == 1) ? Wk : Wv;
    int idx = blockIdx.x * 256 + threadIdx.x;
    int k = idx >> 6, c = idx & 63;
    g_W[(mt * 64 + c) * DM + k] = __float2half(W[k * DH + c]);
}

// ---------------- fused QKV projection: 2-stage, single-fp16 ----------------
__global__ __launch_bounds__(512) void proj_kernel(
    const float* __restrict__ x, const float* __restrict__ bq,
    const float* __restrict__ bk, const float* __restrict__ bv) {
    extern __shared__ char smem[];
    const uint32_t sbase = s_u32(smem);
    const int tid = threadIdx.x, lane = tid & 31, w = tid >> 5;
    const int row0 = blockIdx.x * 128;
    const int bb = row0 >> 11, iloc = row0 & 2047;

    const int wm = w & 3, wn = w >> 2;
    float acc[2][6][4];
    #pragma unroll
    for (int i = 0; i < 2; i++)
        #pragma unroll
        for (int j = 0; j < 6; j++)
            #pragma unroll
            for (int q = 0; q < 4; q++) acc[i][j][q] = 0.f;

    const int xr_r = tid >> 2, xr_c = (tid & 3) * 16;

    auto ldx = [&](int kc, float4* xr) {
        const float4* src = (const float4*)(x + (size_t)(row0 + xr_r) * DM + kc * 64 + xr_c);
        xr[0] = src[0]; xr[1] = src[1]; xr[2] = src[2]; xr[3] = src[3];
    };
    auto convA = [&](const float4* xr, int st) {
        __half* A = (__half*)(smem + st * 46080);
        unsigned short hs[16];
        #pragma unroll
        for (int q = 0; q < 4; q++) {
            float4 v = xr[q];
            hs[q*4+0] = h16(v.x); hs[q*4+1] = h16(v.y);
            hs[q*4+2] = h16(v.z); hs[q*4+3] = h16(v.w);
        }
        uint4* dh = (uint4*)(A + xr_r * 72 + xr_c);
        dh[0] = make_uint4(pk2(hs[0],hs[1]), pk2(hs[2],hs[3]), pk2(hs[4],hs[5]), pk2(hs[6],hs[7]));
        dh[1] = make_uint4(pk2(hs[8],hs[9]), pk2(hs[10],hs[11]), pk2(hs[12],hs[13]), pk2(hs[14],hs[15]));
    };
    auto ldW = [&](int kc, int st) {
        uint32_t bw = sbase + st * 46080 + 18432;
        #pragma unroll
        for (int p = 0; p < 3; p++) {
            int lin = p * 512 + tid, r = lin >> 3, q = lin & 7;
            CPA16(bw + (uint32_t)(r * 144 + q * 16),
                  (const char*)g_W + ((size_t)r * DM + kc * 64) * 2 + q * 16);
        }
        CPA_COMMIT();
    };

    float4 xr[4];
    ldx(0, xr);
    ldW(0, 0);
    convA(xr, 0);
    CPA_WAIT0();
    __syncthreads();

    for (int c = 0; c < 16; c++) {
        const int cur = c & 1;
        if (c < 15) { ldx(c + 1, xr); ldW(c + 1, cur ^ 1); }

        const uint32_t S = sbase + cur * 46080;
        const uint32_t sA = S, sB = S + 18432;
        #pragma unroll
        for (int ks = 0; ks < 4; ks++) {
            const int k0 = ks * 16;
            uint32_t a[2][4];
            #pragma unroll
            for (int mf = 0; mf < 2; mf++) {
                uint32_t off = (uint32_t)((wm * 32 + mf * 16 + (lane & 15)) * 72 +
                                          k0 + ((lane >> 4) << 3)) * 2;
                LDSM4(a[mf][0], a[mf][1], a[mf][2], a[mf][3], sA + off);
            }
            uint32_t b[6][2];
            #pragma unroll
            for (int nb = 0; nb < 3; nb++) {
                uint32_t off = (uint32_t)((wn * 48 + nb * 16 + (lane & 7) + ((lane >> 4) << 3)) * 72 +
                                          k0 + (((lane >> 3) & 1) << 3)) * 2;
                LDSM4(b[2*nb][0], b[2*nb][1], b[2*nb+1][0], b[2*nb+1][1], sB + off);
            }
            #pragma unroll
            for (int mf = 0; mf < 2; mf++)
                #pragma unroll
                for (int nf = 0; nf < 6; nf++)
                    mma_f16(acc[mf][nf], a[mf], b[nf]);
        }
        if (c < 15) { convA(xr, cur ^ 1); CPA_WAIT0(); }
        __syncthreads();
    }

    // epilogue: Q, K fp16 direct; V staged fp32 transposed
    float* sV = (float*)smem;     // [64][132] fp32
    #pragma unroll
    for (int mf = 0; mf < 2; mf++)
        #pragma unroll
        for (int nf = 0; nf < 6; nf++) {
            int gc = wn * 48 + nf * 8 + (lane & 3) * 2;
            int mt = gc >> 6, cm = gc & 63;
            int r0 = wm * 32 + mf * 16 + (lane >> 2);
            #pragma unroll
            for (int h = 0; h < 2; h++) {
                int rl = r0 + h * 8;
                float v0 = acc[mf][nf][h * 2 + 0], v1 = acc[mf][nf][h * 2 + 1];
                if (mt == 0) {
                    size_t o = (size_t)(row0 + rl) * DH + cm;
                    *(uint32_t*)(g_Q + o) = pk2(h16(v0 + bq[cm]), h16(v1 + bq[cm + 1]));
                } else if (mt == 1) {
                    size_t o = (size_t)(row0 + rl) * DH + cm;
                    *(uint32_t*)(g_K + o) = pk2(h16(v0 + bk[cm]), h16(v1 + bk[cm + 1]));
                } else {
                    sV[cm * 132 + rl]       = v0 + bv[cm];
                    sV[(cm + 1) * 132 + rl] = v1 + bv[cm + 1];
                }
            }
        }
    __syncthreads();
    #pragma unroll
    for (int p = 0; p < 4; p++) {
        int lin = p * 512 + tid, r = lin >> 5, q4 = lin & 31;
        *(float4*)(g_Vt + (size_t)(bb * 64 + r) * SEQ + iloc + q4 * 4) =
            *(float4*)(sV + r * 132 + q4 * 4);
    }
}

// ---------------- colsum pass (unchanged) ----------------
__global__ __launch_bounds__(256) void colsum_kernel() {
    extern __shared__ char smem[];
    __shared__ float sred[256];
    const int tid = threadIdx.x, lane = tid & 31, w = tid >> 5;
    const int jt = blockIdx.x, it = blockIdx.y, bb = blockIdx.z;
    const int i0 = it * 128, j0 = jt * 128;
    const uint32_t sbase = s_u32(smem);

    {
        const __half* src[2] = { g_Q, g_K };
        #pragma unroll
        for (int a = 0; a < 2; a++) {
            const int rb = bb * SEQ + ((a == 0) ? i0 : j0);
            #pragma unroll
            for (int p = 0; p < 4; p++) {
                int lin = p * 256 + tid, r = lin >> 3, q = lin & 7;
                CPA16(sbase + a * 18432 + (uint32_t)(r * 144 + q * 16),
                      (const char*)src[a] + ((size_t)(rb + r) * DH) * 2 + q * 16);
            }
        }
        CPA_COMMIT(); CPA_WAIT0();
    }
    __syncthreads();

    const uint32_t sQ = sbase, sK = sbase + 18432;
    const int wm = w & 1, wn = w >> 1;
    float acc[4][4][4];
    #pragma unroll
    for (int i = 0; i < 4; i++)
        #pragma unroll
        for (int j = 0; j < 4; j++)
            #pragma unroll
            for (int q = 0; q < 4; q++) acc[i][j][q] = 0.f;

    #pragma unroll
    for (int ks = 0; ks < 4; ks++) {
        const int k0 = ks * 16;
        uint32_t a[4][4];
        #pragma unroll
        for (int mf = 0; mf < 4; mf++) {
            uint32_t off = (uint32_t)((wm * 64 + mf * 16 + (lane & 15)) * 72 +
                                      k0 + ((lane >> 4) << 3)) * 2;
            LDSM4(a[mf][0], a[mf][1], a[mf][2], a[mf][3], sQ + off);
        }
        uint32_t b[4][2];
        #pragma unroll
        for (int nb = 0; nb < 2; nb++) {
            uint32_t off = (uint32_t)((wn * 32 + nb * 16 + (lane & 7) + ((lane >> 4) << 3)) * 72 +
                                      k0 + (((lane >> 3) & 1) << 3)) * 2;
            LDSM4(b[2*nb][0], b[2*nb][1], b[2*nb+1][0], b[2*nb+1][1], sK + off);
        }
        #pragma unroll
        for (int mf = 0; mf < 4; mf++)
            #pragma unroll
            for (int nf = 0; nf < 4; nf++)
                mma_f16(acc[mf][nf], a[mf], b[nf]);
    }
    __syncthreads();

    __half* Est = (__half*)smem;
    #pragma unroll
    for (int mf = 0; mf < 4; mf++)
        #pragma unroll
        for (int nf = 0; nf < 4; nf++) {
            int col = wn * 32 + nf * 8 + (lane & 3) * 2;
            int r0 = wm * 64 + mf * 16 + (lane >> 2);
            #pragma unroll
            for (int h = 0; h < 2; h++) {
                float e0 = __expf(0.125f * acc[mf][nf][h * 2 + 0]);
                float e1 = __expf(0.125f * acc[mf][nf][h * 2 + 1]);
                *(__half2*)(Est + (r0 + h * 8) * 136 + col) = __floats2half2_rn(e0, e1);
            }
        }
    __syncthreads();
    {
        int col = tid & 127, hf = tid >> 7;
        float s = 0.f;
        #pragma unroll 8
        for (int i = 0; i < 64; i++) s += __half2float(Est[(hf * 64 + i) * 136 + col]);
        sred[tid] = s;
        __syncthreads();
        if (tid < 128)
            g_psum[(bb * ITILES + it) * SEQ + j0 + tid] = sred[tid] + sred[tid + 128];
    }
}

// ---------------- merge psums -> c, V' = c*V -> fp16 ----------------
__global__ __launch_bounds__(256) void merge_scale_kernel() {
    __shared__ float sc[128];
    const int tid = threadIdx.x;
    const int bx = blockIdx.x, bb = blockIdx.y;
    const int ibase = bx * 128;
    if (tid < 128) {
        int j = ibase + tid;
        float s = 0.f;
        #pragma unroll
        for (int it = 0; it < ITILES; it++)
            s += g_psum[(bb * ITILES + it) * SEQ + j];
        sc[tid] = 1.0f / s;
    }
    __syncthreads();
    #pragma unroll
    for (int p = 0; p < 8; p++) {
        int lin = p * 256 + tid, d = lin >> 5, q = lin & 31;
        size_t idx = (size_t)(bb * 64 + d) * SEQ + ibase + q * 4;
        float4 v = *(const float4*)(g_Vt + idx);
        float c0 = sc[q*4], c1 = sc[q*4+1], c2 = sc[q*4+2], c3 = sc[q*4+3];
        __half2 lo = __floats2half2_rn(v.x * c0, v.y * c1);
        __half2 hi = __floats2half2_rn(v.z * c2, v.w * c3);
        *(uint2*)(g_Vf + idx) = make_uint2(
            pk2(__half_as_ushort(__low2half(lo)), __half_as_ushort(__high2half(lo))),
            pk2(__half_as_ushort(__low2half(hi)), __half_as_ushort(__high2half(hi))));
    }
}

// ---------------- fused attention v2: i-tile 64 -> 256 CTAs, 2/SM ----------------
// grid (32,8), block 256 (8 warps). 16 j-chunks of 128.
// smem: sQ @0 (9216) | sP @9216 (17408) | sK[2] @26624 (18432 ea) | sV[2] @63488 (17408 ea)
// total 98304. Epilogue Ost f32 [64][68] (17408 B) reuses sP region.
__global__ __launch_bounds__(256) void attn_kernel(float* __restrict__ out) {
    extern __shared__ char smem[];
    const int tid = threadIdx.x, lane = tid & 31, w = tid >> 5;
    const int it = blockIdx.x, bb = blockIdx.y;
    const int i0 = it * 64;
    const uint32_t sbase = s_u32(smem);
    const uint32_t sQ = sbase, sP = sbase + 9216;
    const uint32_t sKb = sbase + 26624, sVb = sbase + 63488;

    // S-MMA tiling: rows (i): 2 groups of 32 (wm1), cols (j): 4 groups of 32 (wn1)
    const int wm1 = w & 1, wn1 = w >> 1;
    // O-MMA tiling: rows (i): 2 groups of 32 (wm2), cols (d): 4 groups of 16 (wn2)
    const int wm2 = w & 1, wn2 = w >> 1;

    float accO[2][2][4];
    #pragma unroll
    for (int i = 0; i < 2; i++)
        #pragma unroll
        for (int j = 0; j < 2; j++)
            #pragma unroll
            for (int q = 0; q < 4; q++) accO[i][j][q] = 0.f;

    auto issueKV = [&](int c) {
        const int buf = c & 1;
        const int j0 = c * 128;
        #pragma unroll
        for (int p = 0; p < 4; p++) {            // K: 128 rows x 128B
            int lin = p * 256 + tid, r = lin >> 3, q = lin & 7;
            CPA16(sKb + buf * 18432 + (uint32_t)(r * 144 + q * 16),
                  (const char*)g_K + ((size_t)(bb * SEQ + j0 + r) * DH) * 2 + q * 16);
        }
        #pragma unroll
        for (int p = 0; p < 4; p++) {            // V': 64 rows(d) x 256B
            int lin = p * 256 + tid, r = lin >> 4, q = lin & 15;
            CPA16(sVb + buf * 17408 + (uint32_t)(r * 272 + q * 16),
                  (const char*)g_Vf + ((size_t)(bb * 64 + r) * SEQ + j0) * 2 + q * 16);
        }
    };

    // prologue
    #pragma unroll
    for (int p = 0; p < 2; p++) {                // Q: 64 rows x 128B
        int lin = p * 256 + tid, r = lin >> 3, q = lin & 7;
        CPA16(sQ + (uint32_t)(r * 144 + q * 16),
              (const char*)g_Q + ((size_t)(bb * SEQ + i0 + r) * DH) * 2 + q * 16);
    }
    issueKV(0); CPA_COMMIT();
    issueKV(1); CPA_COMMIT();

    for (int c = 0; c < 16; c++) {
        if (c < 15) { CPA_WAIT1(); } else { CPA_WAIT0(); }
        __syncthreads();

        const uint32_t sK = sKb + (c & 1) * 18432;
        const uint32_t sV = sVb + (c & 1) * 17408;

        // ---- S = Q K^T  (64 x 128) ----
        float accS[2][4][4];
        #pragma unroll
        for (int i = 0; i < 2; i++)
            #pragma unroll
            for (int j = 0; j < 4; j++)
                #pragma unroll
                for (int q = 0; q < 4; q++) accS[i][j][q] = 0.f;
        #pragma unroll
        for (int ks = 0; ks < 4; ks++) {
            const int k0 = ks * 16;
            uint32_t a[2][4];
            #pragma unroll
            for (int mf = 0; mf < 2; mf++) {
                uint32_t off = (uint32_t)((wm1 * 32 + mf * 16 + (lane & 15)) * 72 +
                                          k0 + ((lane >> 4) << 3)) * 2;
                LDSM4(a[mf][0], a[mf][1], a[mf][2], a[mf][3], sQ + off);
            }
            uint32_t b[4][2];
            #pragma unroll
            for (int nb = 0; nb < 2; nb++) {
                uint32_t off = (uint32_t)((wn1 * 32 + nb * 16 + (lane & 7) + ((lane >> 4) << 3)) * 72 +
                                          k0 + (((lane >> 3) & 1) << 3)) * 2;
                LDSM4(b[2*nb][0], b[2*nb][1], b[2*nb+1][0], b[2*nb+1][1], sK + off);
            }
            #pragma unroll
            for (int mf = 0; mf < 2; mf++)
                #pragma unroll
                for (int nf = 0; nf < 4; nf++)
                    mma_f16(accS[mf][nf], a[mf], b[nf]);
        }
        // ---- P = exp(S/8) -> sP (fp16, pitch 136) ----
        #pragma unroll
        for (int mf = 0; mf < 2; mf++)
            #pragma unroll
            for (int nf = 0; nf < 4; nf++) {
                int col = wn1 * 32 + nf * 8 + (lane & 3) * 2;
                int r0 = wm1 * 32 + mf * 16 + (lane >> 2);
                #pragma unroll
                for (int h = 0; h < 2; h++) {
                    float e0 = __expf(0.125f * accS[mf][nf][h * 2 + 0]);
                    float e1 = __expf(0.125f * accS[mf][nf][h * 2 + 1]);
                    *(__half2*)((char*)smem + 9216 + ((r0 + h * 8) * 136 + col) * 2) =
                        __floats2half2_rn(e0, e1);
                }
            }
        __syncthreads();
        // ---- O += P V'^T  (64 x 64, k = 128) ----
        #pragma unroll
        for (int ks = 0; ks < 8; ks++) {
            const int k0 = ks * 16;
            uint32_t a[2][4];
            #pragma unroll
            for (int mf = 0; mf < 2; mf++) {
                uint32_t off = (uint32_t)((wm2 * 32 + mf * 16 + (lane & 15)) * 136 +
                                          k0 + ((lane >> 4) << 3)) * 2;
                LDSM4(a[mf][0], a[mf][1], a[mf][2], a[mf][3], sP + off);
            }
            uint32_t b[2][2];
            {
                uint32_t off = (uint32_t)((wn2 * 16 + (lane & 7) + ((lane >> 4) << 3)) * 136 +
                                          k0 + (((lane >> 3) & 1) << 3)) * 2;
                LDSM4(b[0][0], b[0][1], b[1][0], b[1][1], sV + off);
            }
            #pragma unroll
            for (int mf = 0; mf < 2; mf++)
                #pragma unroll
                for (int nf = 0; nf < 2; nf++)
                    mma_f16(accO[mf][nf], a[mf], b[nf]);
        }
        __syncthreads();
        if (c + 2 < 16) { issueKV(c + 2); CPA_COMMIT(); }
    }

    // epilogue: stage O f32 (pitch 68) in sP region, coalesced store
    float* Ost = (float*)((char*)smem + 9216);
    #pragma unroll
    for (int mf = 0; mf < 2; mf++)
        #pragma unroll
        for (int nf = 0; nf < 2; nf++) {
            int col = wn2 * 16 + nf * 8 + (lane & 3) * 2;
            int r0 = wm2 * 32 + mf * 16 + (lane >> 2);
            #pragma unroll
            for (int h = 0; h < 2; h++) {
                Ost[(r0 + h * 8) * 68 + col]     = accO[mf][nf][h * 2 + 0];
                Ost[(r0 + h * 8) * 68 + col + 1] = accO[mf][nf][h * 2 + 1];
            }
        }
    __syncthreads();
    #pragma unroll
    for (int p = 0; p < 4; p++) {
        int lin = p * 256 + tid, r = lin >> 4, c4 = lin & 15;
        *(float4*)(out + ((size_t)(bb * SEQ + i0 + r)) * DH + c4 * 4) =
            *(float4*)(Ost + r * 68 + c4 * 4);
    }
}

// ---------------- launch ----------------
extern "C" void kernel_launch(void* const* d_in, const int* in_sizes, int n_in,
                              void* d_out, int out_size)
{
    const float* x  = (const float*)d_in[0];
    const float* Wq = (const float*)d_in[1];
    const float* bq = (const float*)d_in[2];
    const float* Wk = (const float*)d_in[3];
    const float* bk = (const float*)d_in[4];
    const float* Wv = (const float*)d_in[5];
    const float* bv = (const float*)d_in[6];
    float* out = (float*)d_out;

    cudaFuncSetAttribute(proj_kernel,   cudaFuncAttributeMaxDynamicSharedMemorySize, 92160);
    cudaFuncSetAttribute(colsum_kernel, cudaFuncAttributeMaxDynamicSharedMemorySize, 36864);
    cudaFuncSetAttribute(attn_kernel,   cudaFuncAttributeMaxDynamicSharedMemorySize, 98304);

    split_w_kernel<<<dim3(256, 3), 256>>>(Wq, Wk, Wv);
    proj_kernel<<<128, 512, 92160>>>(x, bq, bk, bv);
    colsum_kernel<<<dim3(16, 16, 8), 256, 36864>>>();
    merge_scale_kernel<<<dim3(16, 8), 256>>>();
    attn_kernel<<<dim3(32, 8), 256, 98304>>>(out);   // 32 i-tiles x 8 batches
}

// round 14
// speedup vs baseline: 1.1198x; 1.1198x over previous
#include <cuda_runtime.h>
#include <cuda_bf16.h>
#include <cuda_fp16.h>
#include <cstdint>

#define BATCH 8
#define SEQ   2048
#define DM    1024
#define DH    64
#define NTOK  (BATCH * SEQ)
#define ITILES 16

// ---------------- device scratch ----------------
__device__ __half g_W[3 * DH * DM];                // [mat*64+c][k], fp16
__device__ __half g_Q[NTOK * DH];                  // Q fp16
__device__ __half g_K[NTOK * DH];                  // K fp16
__device__ float  g_Vt[BATCH * DH * SEQ];          // V fp32, [b][d][i]
__device__ __half g_E[(size_t)NTOK * SEQ];         // exp(S) fp16, [b,i,j]
__device__ __half g_Vf[BATCH * DH * SEQ];          // V' = diag(c) V, fp16, [b][d][i]
__device__ float  g_csum[BATCH * SEQ];             // atomic column sums

// ---------------- helpers ----------------
__device__ __forceinline__ uint32_t s_u32(const void* p) {
    uint32_t a;
    asm("{ .reg .u64 t; cvta.to.shared.u64 t, %1; cvt.u32.u64 %0, t; }" : "=r"(a) : "l"(p));
    return a;
}
#define LDSM4(r0, r1, r2, r3, addr) \
    asm volatile("ldmatrix.sync.aligned.m8n8.x4.shared.b16 {%0,%1,%2,%3}, [%4];" \
                 : "=r"(r0), "=r"(r1), "=r"(r2), "=r"(r3) : "r"(addr))
#define CPA16(dst, src) \
    asm volatile("cp.async.cg.shared.global [%0], [%1], 16;" :: "r"(dst), "l"(src))
#define CPA_COMMIT() asm volatile("cp.async.commit_group;" ::: "memory")
#define CPA_WAIT2()  asm volatile("cp.async.wait_group 2;" ::: "memory")
#define CPA_WAIT1()  asm volatile("cp.async.wait_group 1;" ::: "memory")
#define CPA_WAIT0()  asm volatile("cp.async.wait_group 0;" ::: "memory")

__device__ __forceinline__ void mma_f16(float* c, const uint32_t* a, const uint32_t* b) {
    asm volatile(
        "mma.sync.aligned.m16n8k16.row.col.f32.f16.f16.f32 "
        "{%0,%1,%2,%3}, {%4,%5,%6,%7}, {%8,%9}, {%0,%1,%2,%3};"
        : "+f"(c[0]), "+f"(c[1]), "+f"(c[2]), "+f"(c[3])
        : "r"(a[0]), "r"(a[1]), "r"(a[2]), "r"(a[3]), "r"(b[0]), "r"(b[1]));
}
__device__ __forceinline__ uint32_t pk2(unsigned short a, unsigned short b) {
    return (uint32_t)a | ((uint32_t)b << 16);
}
__device__ __forceinline__ unsigned short h16(float v) {
    return __half_as_ushort(__float2half(v));
}

// ---------------- W -> fp16 transpose (+ zero g_csum for this launch) ----------------
__global__ __launch_bounds__(256) void split_w_kernel(
    const float* __restrict__ Wq, const float* __restrict__ Wk, const float* __restrict__ Wv) {
    int mt = blockIdx.y;
    const float* W = (mt == 0) ? Wq : (mt == 1) ? Wk : Wv;
    int idx = blockIdx.x * 256 + threadIdx.x;
    int k = idx >> 6, c = idx & 63;
    g_W[(mt * 64 + c) * DM + k] = __float2half(W[k * DH + c]);
    if (mt == 0 && idx < BATCH * SEQ) g_csum[idx] = 0.f;
}

// ---------------- fused QKV projection: 2-stage, single-fp16 ----------------
// grid 128, block 512 (16 warps 4x4). Stage (46080 B x2): A @0 (18432), B @18432 (27648)
__global__ __launch_bounds__(512) void proj_kernel(
    const float* __restrict__ x, const float* __restrict__ bq,
    const float* __restrict__ bk, const float* __restrict__ bv) {
    extern __shared__ char smem[];
    const uint32_t sbase = s_u32(smem);
    const int tid = threadIdx.x, lane = tid & 31, w = tid >> 5;
    const int row0 = blockIdx.x * 128;
    const int bb = row0 >> 11, iloc = row0 & 2047;

    const int wm = w & 3, wn = w >> 2;          // rows wm*32, cols wn*48
    float acc[2][6][4];
    #pragma unroll
    for (int i = 0; i < 2; i++)
        #pragma unroll
        for (int j = 0; j < 6; j++)
            #pragma unroll
            for (int q = 0; q < 4; q++) acc[i][j][q] = 0.f;

    const int xr_r = tid >> 2, xr_c = (tid & 3) * 16;

    auto ldx = [&](int kc, float4* xr) {
        const float4* src = (const float4*)(x + (size_t)(row0 + xr_r) * DM + kc * 64 + xr_c);
        xr[0] = src[0]; xr[1] = src[1]; xr[2] = src[2]; xr[3] = src[3];
    };
    auto convA = [&](const float4* xr, int st) {
        __half* A = (__half*)(smem + st * 46080);
        unsigned short hs[16];
        #pragma unroll
        for (int q = 0; q < 4; q++) {
            float4 v = xr[q];
            hs[q*4+0] = h16(v.x); hs[q*4+1] = h16(v.y);
            hs[q*4+2] = h16(v.z); hs[q*4+3] = h16(v.w);
        }
        uint4* dh = (uint4*)(A + xr_r * 72 + xr_c);
        dh[0] = make_uint4(pk2(hs[0],hs[1]), pk2(hs[2],hs[3]), pk2(hs[4],hs[5]), pk2(hs[6],hs[7]));
        dh[1] = make_uint4(pk2(hs[8],hs[9]), pk2(hs[10],hs[11]), pk2(hs[12],hs[13]), pk2(hs[14],hs[15]));
    };
    auto ldW = [&](int kc, int st) {
        uint32_t bw = sbase + st * 46080 + 18432;
        #pragma unroll
        for (int p = 0; p < 3; p++) {
            int lin = p * 512 + tid, r = lin >> 3, q = lin & 7;
            CPA16(bw + (uint32_t)(r * 144 + q * 16),
                  (const char*)g_W + ((size_t)r * DM + kc * 64) * 2 + q * 16);
        }
        CPA_COMMIT();
    };

    float4 xr[4];
    ldx(0, xr);
    ldW(0, 0);
    convA(xr, 0);
    CPA_WAIT0();
    __syncthreads();

    for (int c = 0; c < 16; c++) {
        const int cur = c & 1;
        if (c < 15) { ldx(c + 1, xr); ldW(c + 1, cur ^ 1); }

        const uint32_t S = sbase + cur * 46080;
        const uint32_t sA = S, sB = S + 18432;
        #pragma unroll
        for (int ks = 0; ks < 4; ks++) {
            const int k0 = ks * 16;
            uint32_t a[2][4];
            #pragma unroll
            for (int mf = 0; mf < 2; mf++) {
                uint32_t off = (uint32_t)((wm * 32 + mf * 16 + (lane & 15)) * 72 +
                                          k0 + ((lane >> 4) << 3)) * 2;
                LDSM4(a[mf][0], a[mf][1], a[mf][2], a[mf][3], sA + off);
            }
            uint32_t b[6][2];
            #pragma unroll
            for (int nb = 0; nb < 3; nb++) {
                uint32_t off = (uint32_t)((wn * 48 + nb * 16 + (lane & 7) + ((lane >> 4) << 3)) * 72 +
                                          k0 + (((lane >> 3) & 1) << 3)) * 2;
                LDSM4(b[2*nb][0], b[2*nb][1], b[2*nb+1][0], b[2*nb+1][1], sB + off);
            }
            #pragma unroll
            for (int mf = 0; mf < 2; mf++)
                #pragma unroll
                for (int nf = 0; nf < 6; nf++)
                    mma_f16(acc[mf][nf], a[mf], b[nf]);
        }
        if (c < 15) { convA(xr, cur ^ 1); CPA_WAIT0(); }
        __syncthreads();
    }

    // epilogue: Q, K single fp16 direct; V staged fp32 transposed
    float* sV = (float*)smem;     // [64][132] fp32 = 33792 B
    #pragma unroll
    for (int mf = 0; mf < 2; mf++)
        #pragma unroll
        for (int nf = 0; nf < 6; nf++) {
            int gc = wn * 48 + nf * 8 + (lane & 3) * 2;
            int mt = gc >> 6, cm = gc & 63;
            int r0 = wm * 32 + mf * 16 + (lane >> 2);
            #pragma unroll
            for (int h = 0; h < 2; h++) {
                int rl = r0 + h * 8;
                float v0 = acc[mf][nf][h * 2 + 0], v1 = acc[mf][nf][h * 2 + 1];
                if (mt == 0) {
                    size_t o = (size_t)(row0 + rl) * DH + cm;
                    *(uint32_t*)(g_Q + o) = pk2(h16(v0 + bq[cm]), h16(v1 + bq[cm + 1]));
                } else if (mt == 1) {
                    size_t o = (size_t)(row0 + rl) * DH + cm;
                    *(uint32_t*)(g_K + o) = pk2(h16(v0 + bk[cm]), h16(v1 + bk[cm + 1]));
                } else {
                    sV[cm * 132 + rl]       = v0 + bv[cm];
                    sV[(cm + 1) * 132 + rl] = v1 + bv[cm + 1];
                }
            }
        }
    __syncthreads();
    #pragma unroll
    for (int p = 0; p < 4; p++) {
        int lin = p * 512 + tid, r = lin >> 5, q4 = lin & 31;
        *(float4*)(g_Vt + (size_t)(bb * 64 + r) * SEQ + iloc + q4 * 4) =
            *(float4*)(sV + r * 132 + q4 * 4);
    }
}

// ---------------- scores -> E = exp(S) (fp16) + atomic column sums ----------------
// grid (16,16,8), block 256. smem: Q,K [128][72]h (36864 B); reused as Est fp16 pitch 136.
__global__ __launch_bounds__(256) void scores_kernel() {
    extern __shared__ char smem[];
    __shared__ float sred[256];
    const int tid = threadIdx.x, lane = tid & 31, w = tid >> 5;
    const int jt = blockIdx.x, it = blockIdx.y, bb = blockIdx.z;
    const int i0 = it * 128, j0 = jt * 128;
    const uint32_t sbase = s_u32(smem);

    {
        const __half* src[2] = { g_Q, g_K };
        #pragma unroll
        for (int a = 0; a < 2; a++) {
            const int rb = bb * SEQ + ((a == 0) ? i0 : j0);
            #pragma unroll
            for (int p = 0; p < 4; p++) {
                int lin = p * 256 + tid, r = lin >> 3, q = lin & 7;
                CPA16(sbase + a * 18432 + (uint32_t)(r * 144 + q * 16),
                      (const char*)src[a] + ((size_t)(rb + r) * DH) * 2 + q * 16);
            }
        }
        CPA_COMMIT(); CPA_WAIT0();
    }
    __syncthreads();

    const uint32_t sQ = sbase, sK = sbase + 18432;
    const int wm = w & 1, wn = w >> 1;          // rows wm*64, cols wn*32
    float acc[4][4][4];
    #pragma unroll
    for (int i = 0; i < 4; i++)
        #pragma unroll
        for (int j = 0; j < 4; j++)
            #pragma unroll
            for (int q = 0; q < 4; q++) acc[i][j][q] = 0.f;

    #pragma unroll
    for (int ks = 0; ks < 4; ks++) {
        const int k0 = ks * 16;
        uint32_t a[4][4];
        #pragma unroll
        for (int mf = 0; mf < 4; mf++) {
            uint32_t off = (uint32_t)((wm * 64 + mf * 16 + (lane & 15)) * 72 +
                                      k0 + ((lane >> 4) << 3)) * 2;
            LDSM4(a[mf][0], a[mf][1], a[mf][2], a[mf][3], sQ + off);
        }
        uint32_t b[4][2];
        #pragma unroll
        for (int nb = 0; nb < 2; nb++) {
            uint32_t off = (uint32_t)((wn * 32 + nb * 16 + (lane & 7) + ((lane >> 4) << 3)) * 72 +
                                      k0 + (((lane >> 3) & 1) << 3)) * 2;
            LDSM4(b[2*nb][0], b[2*nb][1], b[2*nb+1][0], b[2*nb+1][1], sK + off);
        }
        #pragma unroll
        for (int mf = 0; mf < 4; mf++)
            #pragma unroll
            for (int nf = 0; nf < 4; nf++)
                mma_f16(acc[mf][nf], a[mf], b[nf]);
    }
    __syncthreads();

    // stage E = exp(S/8) as fp16 (pitch 136 halves)
    __half* Est = (__half*)smem;
    #pragma unroll
    for (int mf = 0; mf < 4; mf++)
        #pragma unroll
        for (int nf = 0; nf < 4; nf++) {
            int col = wn * 32 + nf * 8 + (lane & 3) * 2;
            int r0 = wm * 64 + mf * 16 + (lane >> 2);
            #pragma unroll
            for (int h = 0; h < 2; h++) {
                float e0 = __expf(0.125f * acc[mf][nf][h * 2 + 0]);
                float e1 = __expf(0.125f * acc[mf][nf][h * 2 + 1]);
                *(__half2*)(Est + (r0 + h * 8) * 136 + col) = __floats2half2_rn(e0, e1);
            }
        }
    __syncthreads();
    // coalesced fp16 E store
    #pragma unroll
    for (int p = 0; p < 8; p++) {
        int lin = p * 256 + tid, r = lin >> 4, c8 = lin & 15;
        *(uint4*)((char*)g_E + ((size_t)(bb * SEQ + i0 + r) * SEQ + j0) * 2 + c8 * 16) =
            *(uint4*)((char*)Est + r * 272 + c8 * 16);
    }
    // per-column partial sums (2-way row split) + atomic accumulate
    {
        int col = tid & 127, hf = tid >> 7;
        float s = 0.f;
        #pragma unroll 8
        for (int i = 0; i < 64; i++) s += __half2float(Est[(hf * 64 + i) * 136 + col]);
        sred[tid] = s;
        __syncthreads();
        if (tid < 128)
            atomicAdd(&g_csum[bb * SEQ + j0 + tid], sred[tid] + sred[tid + 128]);
    }
}

// ---------------- V' = diag(1/csum) V -> fp16 (float4-vectorized) ----------------
__global__ __launch_bounds__(256) void scale_v_kernel() {
    int t4 = blockIdx.x * 256 + threadIdx.x;      // 0 .. 262143
    int idx = t4 * 4;                             // element index in [b][d][i]
    int bb = idx >> 17, i = idx & 2047;
    float4 v = *(const float4*)(g_Vt + idx);
    float4 s = *(const float4*)(g_csum + bb * SEQ + i);
    __half2 lo = __floats2half2_rn(v.x / s.x, v.y / s.y);
    __half2 hi = __floats2half2_rn(v.z / s.z, v.w / s.w);
    *(uint2*)(g_Vf + idx) = make_uint2(
        pk2(__half_as_ushort(__low2half(lo)), __half_as_ushort(__high2half(lo))),
        pk2(__half_as_ushort(__low2half(hi)), __half_as_ushort(__high2half(hi))));
}

// ---------------- output: 3-stage fp16 GEMM O = E @ V' ----------------
// grid (32,8), block 128 (4 warps 2x2). C [64][64]; 16 j-chunks of 128.
// per stage: E [64][136]h (17408 B) + V [64][136]h -> 34816; x3 = 104448
__global__ __launch_bounds__(128) void out_kernel(float* __restrict__ out) {
    extern __shared__ char smem[];
    const int tid = threadIdx.x, lane = tid & 31, w = tid >> 5;
    const int it = blockIdx.x, bb = blockIdx.y;
    const int i0 = it * 64;
    const uint32_t sbase = s_u32(smem);

    const int wm = w & 1, wn = w >> 1;
    float acc[2][4][4];
    #pragma unroll
    for (int i = 0; i < 2; i++)
        #pragma unroll
        for (int j = 0; j < 4; j++)
            #pragma unroll
            for (int q = 0; q < 4; q++) acc[i][j][q] = 0.f;

    const char* Eg = (const char*)g_E;
    const char* Vg = (const char*)g_Vf;

    auto issue = [&](int c) {
        const uint32_t base = sbase + (c % 3) * 34816;
        const int j0 = c * 128;
        #pragma unroll
        for (int p = 0; p < 8; p++) {
            int lin = p * 128 + tid, r = lin >> 4, q = lin & 15;
            CPA16(base + (uint32_t)(r * 272 + q * 16),
                  Eg + ((size_t)(bb * SEQ + i0 + r) * SEQ + j0) * 2 + q * 16);
        }
        #pragma unroll
        for (int p = 0; p < 8; p++) {
            int lin = p * 128 + tid, r = lin >> 4, q = lin & 15;
            CPA16(base + 17408 + (uint32_t)(r * 272 + q * 16),
                  Vg + ((size_t)(bb * 64 + r) * SEQ + j0) * 2 + q * 16);
        }
        CPA_COMMIT();
    };

    issue(0); issue(1);
    for (int c = 0; c < 16; c++) {
        if (c + 2 < 16) { issue(c + 2); CPA_WAIT2(); }
        else if (c + 1 < 16) { CPA_WAIT1(); }
        else { CPA_WAIT0(); }
        __syncthreads();

        const uint32_t base = sbase + (c % 3) * 34816;
        const uint32_t sE = base, sV = base + 17408;
        #pragma unroll
        for (int ks = 0; ks < 8; ks++) {
            const int k0 = ks * 16;
            uint32_t a[2][4];
            #pragma unroll
            for (int mf = 0; mf < 2; mf++) {
                uint32_t off = (uint32_t)((wm * 32 + mf * 16 + (lane & 15)) * 136 +
                                          k0 + ((lane >> 4) << 3)) * 2;
                LDSM4(a[mf][0], a[mf][1], a[mf][2], a[mf][3], sE + off);
            }
            uint32_t b[4][2];
            #pragma unroll
            for (int nb = 0; nb < 2; nb++) {
                uint32_t off = (uint32_t)((wn * 32 + nb * 16 + (lane & 7) + ((lane >> 4) << 3)) * 136 +
                                          k0 + (((lane >> 3) & 1) << 3)) * 2;
                LDSM4(b[2*nb][0], b[2*nb][1], b[2*nb+1][0], b[2*nb+1][1], sV + off);
            }
            #pragma unroll
            for (int mf = 0; mf < 2; mf++)
                #pragma unroll
                for (int nf = 0; nf < 4; nf++)
                    mma_f16(acc[mf][nf], a[mf], b[nf]);
        }
        __syncthreads();
    }

    // epilogue: stage f32 (pitch 68) then coalesced store
    float* Ost = (float*)smem;
    #pragma unroll
    for (int mf = 0; mf < 2; mf++)
        #pragma unroll
        for (int nf = 0; nf < 4; nf++) {
            int col = wn * 32 + nf * 8 + (lane & 3) * 2;
            int r0 = wm * 32 + mf * 16 + (lane >> 2);
            #pragma unroll
            for (int h = 0; h < 2; h++) {
                Ost[(r0 + h * 8) * 68 + col]     = acc[mf][nf][h * 2 + 0];
                Ost[(r0 + h * 8) * 68 + col + 1] = acc[mf][nf][h * 2 + 1];
            }
        }
    __syncthreads();
    #pragma unroll
    for (int p = 0; p < 8; p++) {
        int lin = p * 128 + tid, r = lin >> 4, c4 = lin & 15;
        *(float4*)(out + ((size_t)(bb * SEQ + i0 + r)) * DH + c4 * 4) =
            *(float4*)(Ost + r * 68 + c4 * 4);
    }
}

// ---------------- launch ----------------
extern "C" void kernel_launch(void* const* d_in, const int* in_sizes, int n_in,
                              void* d_out, int out_size)
{
    const float* x  = (const float*)d_in[0];
    const float* Wq = (const float*)d_in[1];
    const float* bq = (const float*)d_in[2];
    const float* Wk = (const float*)d_in[3];
    const float* bk = (const float*)d_in[4];
    const float* Wv = (const float*)d_in[5];
    const float* bv = (const float*)d_in[6];
    float* out = (float*)d_out;

    cudaFuncSetAttribute(proj_kernel,   cudaFuncAttributeMaxDynamicSharedMemorySize, 92160);
    cudaFuncSetAttribute(scores_kernel, cudaFuncAttributeMaxDynamicSharedMemorySize, 36864);
    cudaFuncSetAttribute(out_kernel,    cudaFuncAttributeMaxDynamicSharedMemorySize, 104448);

    split_w_kernel<<<dim3(256, 3), 256>>>(Wq, Wk, Wv);   // also zeroes g_csum
    proj_kernel<<<128, 512, 92160>>>(x, bq, bk, bv);
    scores_kernel<<<dim3(16, 16, 8), 256, 36864>>>();
    scale_v_kernel<<<1024, 256>>>();
    out_kernel<<<dim3(32, 8), 128, 104448>>>(out);
}

// round 15
// speedup vs baseline: 1.1396x; 1.0177x over previous
#include <cuda_runtime.h>
#include <cuda_bf16.h>
#include <cuda_fp16.h>
#include <cstdint>

#define BATCH 8
#define SEQ   2048
#define DM    1024
#define DH    64
#define NTOK  (BATCH * SEQ)
#define ITILES 16

// ---------------- device scratch ----------------
__device__ __half g_W[3 * DH * DM];                // [mat*64+c][k], fp16
__device__ __half g_Q[NTOK * DH];                  // Q fp16
__device__ __half g_K[NTOK * DH];                  // K fp16
__device__ float  g_Vt[BATCH * DH * SEQ];          // V fp32, [b][d][i]
__device__ __half g_E[(size_t)NTOK * SEQ];         // exp(S) fp16, [b,i,j]
__device__ __half g_Vf[BATCH * DH * SEQ];          // V' = diag(c) V, fp16, [b][d][i]
__device__ float  g_csum[BATCH * SEQ];             // atomic column sums

// ---------------- helpers ----------------
__device__ __forceinline__ uint32_t s_u32(const void* p) {
    uint32_t a;
    asm("{ .reg .u64 t; cvta.to.shared.u64 t, %1; cvt.u32.u64 %0, t; }" : "=r"(a) : "l"(p));
    return a;
}
#define LDSM4(r0, r1, r2, r3, addr) \
    asm volatile("ldmatrix.sync.aligned.m8n8.x4.shared.b16 {%0,%1,%2,%3}, [%4];" \
                 : "=r"(r0), "=r"(r1), "=r"(r2), "=r"(r3) : "r"(addr))
#define CPA16(dst, src) \
    asm volatile("cp.async.cg.shared.global [%0], [%1], 16;" :: "r"(dst), "l"(src))
#define CPA_COMMIT() asm volatile("cp.async.commit_group;" ::: "memory")
#define CPA_WAIT2()  asm volatile("cp.async.wait_group 2;" ::: "memory")
#define CPA_WAIT1()  asm volatile("cp.async.wait_group 1;" ::: "memory")
#define CPA_WAIT0()  asm volatile("cp.async.wait_group 0;" ::: "memory")

__device__ __forceinline__ void mma_f16(float* c, const uint32_t* a, const uint32_t* b) {
    asm volatile(
        "mma.sync.aligned.m16n8k16.row.col.f32.f16.f16.f32 "
        "{%0,%1,%2,%3}, {%4,%5,%6,%7}, {%8,%9}, {%0,%1,%2,%3};"
        : "+f"(c[0]), "+f"(c[1]), "+f"(c[2]), "+f"(c[3])
        : "r"(a[0]), "r"(a[1]), "r"(a[2]), "r"(a[3]), "r"(b[0]), "r"(b[1]));
}
__device__ __forceinline__ uint32_t pk2(unsigned short a, unsigned short b) {
    return (uint32_t)a | ((uint32_t)b << 16);
}
__device__ __forceinline__ unsigned short h16(float v) {
    return __half_as_ushort(__float2half(v));
}

// ---------------- W -> fp16 transpose (+ zero g_csum for this launch) ----------------
__global__ __launch_bounds__(256) void split_w_kernel(
    const float* __restrict__ Wq, const float* __restrict__ Wk, const float* __restrict__ Wv) {
    int mt = blockIdx.y;
    const float* W = (mt == 0) ? Wq : (mt == 1) ? Wk : Wv;
    int idx = blockIdx.x * 256 + threadIdx.x;
    int k = idx >> 6, c = idx & 63;
    g_W[(mt * 64 + c) * DM + k] = __float2half(W[k * DH + c]);
    if (mt == 0 && idx < BATCH * SEQ) g_csum[idx] = 0.f;
}

// ---------------- fused QKV projection v2: 64-row tiles, 256 CTAs ----------------
// grid 256, block 256 (8 warps 2x4). Stage (36864 B x2): A[64][72] @0 (9216), B[192][72] @9216 (27648)
__global__ __launch_bounds__(256) void proj_kernel(
    const float* __restrict__ x, const float* __restrict__ bq,
    const float* __restrict__ bk, const float* __restrict__ bv) {
    extern __shared__ char smem[];
    const uint32_t sbase = s_u32(smem);
    const int tid = threadIdx.x, lane = tid & 31, w = tid >> 5;
    const int row0 = blockIdx.x * 64;
    const int bb = row0 >> 11, iloc = row0 & 2047;

    const int wm = w & 1, wn = w >> 1;          // rows wm*32, cols wn*48
    float acc[2][6][4];
    #pragma unroll
    for (int i = 0; i < 2; i++)
        #pragma unroll
        for (int j = 0; j < 6; j++)
            #pragma unroll
            for (int q = 0; q < 4; q++) acc[i][j][q] = 0.f;

    const int xr_r = tid >> 2, xr_c = (tid & 3) * 16;   // 64 rows x 64 cols per chunk

    auto ldx = [&](int kc, float4* xr) {
        const float4* src = (const float4*)(x + (size_t)(row0 + xr_r) * DM + kc * 64 + xr_c);
        xr[0] = src[0]; xr[1] = src[1]; xr[2] = src[2]; xr[3] = src[3];
    };
    auto convA = [&](const float4* xr, int st) {
        __half* A = (__half*)(smem + st * 36864);
        unsigned short hs[16];
        #pragma unroll
        for (int q = 0; q < 4; q++) {
            float4 v = xr[q];
            hs[q*4+0] = h16(v.x); hs[q*4+1] = h16(v.y);
            hs[q*4+2] = h16(v.z); hs[q*4+3] = h16(v.w);
        }
        uint4* dh = (uint4*)(A + xr_r * 72 + xr_c);
        dh[0] = make_uint4(pk2(hs[0],hs[1]), pk2(hs[2],hs[3]), pk2(hs[4],hs[5]), pk2(hs[6],hs[7]));
        dh[1] = make_uint4(pk2(hs[8],hs[9]), pk2(hs[10],hs[11]), pk2(hs[12],hs[13]), pk2(hs[14],hs[15]));
    };
    auto ldW = [&](int kc, int st) {
        uint32_t bw = sbase + st * 36864 + 9216;
        #pragma unroll
        for (int p = 0; p < 6; p++) {
            int lin = p * 256 + tid, r = lin >> 3, q = lin & 7;
            CPA16(bw + (uint32_t)(r * 144 + q * 16),
                  (const char*)g_W + ((size_t)r * DM + kc * 64) * 2 + q * 16);
        }
        CPA_COMMIT();
    };

    float4 xr[4];
    ldx(0, xr);
    ldW(0, 0);
    convA(xr, 0);
    CPA_WAIT0();
    __syncthreads();

    for (int c = 0; c < 16; c++) {
        const int cur = c & 1;
        if (c < 15) { ldx(c + 1, xr); ldW(c + 1, cur ^ 1); }

        const uint32_t S = sbase + cur * 36864;
        const uint32_t sA = S, sB = S + 9216;
        #pragma unroll
        for (int ks = 0; ks < 4; ks++) {
            const int k0 = ks * 16;
            uint32_t a[2][4];
            #pragma unroll
            for (int mf = 0; mf < 2; mf++) {
                uint32_t off = (uint32_t)((wm * 32 + mf * 16 + (lane & 15)) * 72 +
                                          k0 + ((lane >> 4) << 3)) * 2;
                LDSM4(a[mf][0], a[mf][1], a[mf][2], a[mf][3], sA + off);
            }
            uint32_t b[6][2];
            #pragma unroll
            for (int nb = 0; nb < 3; nb++) {
                uint32_t off = (uint32_t)((wn * 48 + nb * 16 + (lane & 7) + ((lane >> 4) << 3)) * 72 +
                                          k0 + (((lane >> 3) & 1) << 3)) * 2;
                LDSM4(b[2*nb][0], b[2*nb][1], b[2*nb+1][0], b[2*nb+1][1], sB + off);
            }
            #pragma unroll
            for (int mf = 0; mf < 2; mf++)
                #pragma unroll
                for (int nf = 0; nf < 6; nf++)
                    mma_f16(acc[mf][nf], a[mf], b[nf]);
        }
        if (c < 15) { convA(xr, cur ^ 1); CPA_WAIT0(); }
        __syncthreads();
    }

    // epilogue: Q, K fp16 direct; V staged fp32 transposed ([64 d][68] pitch)
    float* sV = (float*)smem;     // 64*68*4 = 17408 B
    #pragma unroll
    for (int mf = 0; mf < 2; mf++)
        #pragma unroll
        for (int nf = 0; nf < 6; nf++) {
            int gc = wn * 48 + nf * 8 + (lane & 3) * 2;
            int mt = gc >> 6, cm = gc & 63;
            int r0 = wm * 32 + mf * 16 + (lane >> 2);
            #pragma unroll
            for (int h = 0; h < 2; h++) {
                int rl = r0 + h * 8;
                float v0 = acc[mf][nf][h * 2 + 0], v1 = acc[mf][nf][h * 2 + 1];
                if (mt == 0) {
                    size_t o = (size_t)(row0 + rl) * DH + cm;
                    *(uint32_t*)(g_Q + o) = pk2(h16(v0 + bq[cm]), h16(v1 + bq[cm + 1]));
                } else if (mt == 1) {
                    size_t o = (size_t)(row0 + rl) * DH + cm;
                    *(uint32_t*)(g_K + o) = pk2(h16(v0 + bk[cm]), h16(v1 + bk[cm + 1]));
                } else {
                    sV[cm * 68 + rl]       = v0 + bv[cm];
                    sV[(cm + 1) * 68 + rl] = v1 + bv[cm + 1];
                }
            }
        }
    __syncthreads();
    // transposed V store: 64 d-rows x 64 i = 1024 float4
    #pragma unroll
    for (int p = 0; p < 4; p++) {
        int lin = p * 256 + tid, r = lin >> 4, q4 = lin & 15;
        *(float4*)(g_Vt + (size_t)(bb * 64 + r) * SEQ + iloc + q4 * 4) =
            *(float4*)(sV + r * 68 + q4 * 4);
    }
}

// ---------------- scores -> E = exp(S) (fp16) + atomic column sums ----------------
// grid (16,16,8), block 256. smem: Q,K [128][72]h (36864 B); reused as Est fp16 pitch 136.
__global__ __launch_bounds__(256) void scores_kernel() {
    extern __shared__ char smem[];
    __shared__ float sred[256];
    const int tid = threadIdx.x, lane = tid & 31, w = tid >> 5;
    const int jt = blockIdx.x, it = blockIdx.y, bb = blockIdx.z;
    const int i0 = it * 128, j0 = jt * 128;
    const uint32_t sbase = s_u32(smem);

    {
        const __half* src[2] = { g_Q, g_K };
        #pragma unroll
        for (int a = 0; a < 2; a++) {
            const int rb = bb * SEQ + ((a == 0) ? i0 : j0);
            #pragma unroll
            for (int p = 0; p < 4; p++) {
                int lin = p * 256 + tid, r = lin >> 3, q = lin & 7;
                CPA16(sbase + a * 18432 + (uint32_t)(r * 144 + q * 16),
                      (const char*)src[a] + ((size_t)(rb + r) * DH) * 2 + q * 16);
            }
        }
        CPA_COMMIT(); CPA_WAIT0();
    }
    __syncthreads();

    const uint32_t sQ = sbase, sK = sbase + 18432;
    const int wm = w & 1, wn = w >> 1;          // rows wm*64, cols wn*32
    float acc[4][4][4];
    #pragma unroll
    for (int i = 0; i < 4; i++)
        #pragma unroll
        for (int j = 0; j < 4; j++)
            #pragma unroll
            for (int q = 0; q < 4; q++) acc[i][j][q] = 0.f;

    #pragma unroll
    for (int ks = 0; ks < 4; ks++) {
        const int k0 = ks * 16;
        uint32_t a[4][4];
        #pragma unroll
        for (int mf = 0; mf < 4; mf++) {
            uint32_t off = (uint32_t)((wm * 64 + mf * 16 + (lane & 15)) * 72 +
                                      k0 + ((lane >> 4) << 3)) * 2;
            LDSM4(a[mf][0], a[mf][1], a[mf][2], a[mf][3], sQ + off);
        }
        uint32_t b[4][2];
        #pragma unroll
        for (int nb = 0; nb < 2; nb++) {
            uint32_t off = (uint32_t)((wn * 32 + nb * 16 + (lane & 7) + ((lane >> 4) << 3)) * 72 +
                                      k0 + (((lane >> 3) & 1) << 3)) * 2;
            LDSM4(b[2*nb][0], b[2*nb][1], b[2*nb+1][0], b[2*nb+1][1], sK + off);
        }
        #pragma unroll
        for (int mf = 0; mf < 4; mf++)
            #pragma unroll
            for (int nf = 0; nf < 4; nf++)
                mma_f16(acc[mf][nf], a[mf], b[nf]);
    }
    __syncthreads();

    // stage E = exp(S/8) as fp16 (pitch 136 halves)
    __half* Est = (__half*)smem;
    #pragma unroll
    for (int mf = 0; mf < 4; mf++)
        #pragma unroll
        for (int nf = 0; nf < 4; nf++) {
            int col = wn * 32 + nf * 8 + (lane & 3) * 2;
            int r0 = wm * 64 + mf * 16 + (lane >> 2);
            #pragma unroll
            for (int h = 0; h < 2; h++) {
                float e0 = __expf(0.125f * acc[mf][nf][h * 2 + 0]);
                float e1 = __expf(0.125f * acc[mf][nf][h * 2 + 1]);
                *(__half2*)(Est + (r0 + h * 8) * 136 + col) = __floats2half2_rn(e0, e1);
            }
        }
    __syncthreads();
    // coalesced fp16 E store
    #pragma unroll
    for (int p = 0; p < 8; p++) {
        int lin = p * 256 + tid, r = lin >> 4, c8 = lin & 15;
        *(uint4*)((char*)g_E + ((size_t)(bb * SEQ + i0 + r) * SEQ + j0) * 2 + c8 * 16) =
            *(uint4*)((char*)Est + r * 272 + c8 * 16);
    }
    // per-column partial sums (2-way row split) + atomic accumulate
    {
        int col = tid & 127, hf = tid >> 7;
        float s = 0.f;
        #pragma unroll 8
        for (int i = 0; i < 64; i++) s += __half2float(Est[(hf * 64 + i) * 136 + col]);
        sred[tid] = s;
        __syncthreads();
        if (tid < 128)
            atomicAdd(&g_csum[bb * SEQ + j0 + tid], sred[tid] + sred[tid + 128]);
    }
}

// ---------------- V' = diag(1/csum) V -> fp16 (8 elems/thread, fast div) ----------------
__global__ __launch_bounds__(256) void scale_v_kernel() {
    int t = blockIdx.x * 256 + threadIdx.x;       // 131072 threads
    int idx = t * 8;
    int bb = idx >> 17, i = idx & 2047;
    float4 v0 = *(const float4*)(g_Vt + idx);
    float4 v1 = *(const float4*)(g_Vt + idx + 4);
    float4 s0 = *(const float4*)(g_csum + bb * SEQ + i);
    float4 s1 = *(const float4*)(g_csum + bb * SEQ + i + 4);
    __half2 a = __floats2half2_rn(__fdividef(v0.x, s0.x), __fdividef(v0.y, s0.y));
    __half2 b = __floats2half2_rn(__fdividef(v0.z, s0.z), __fdividef(v0.w, s0.w));
    __half2 c = __floats2half2_rn(__fdividef(v1.x, s1.x), __fdividef(v1.y, s1.y));
    __half2 d = __floats2half2_rn(__fdividef(v1.z, s1.z), __fdividef(v1.w, s1.w));
    *(uint4*)(g_Vf + idx) = make_uint4(
        pk2(__half_as_ushort(__low2half(a)), __half_as_ushort(__high2half(a))),
        pk2(__half_as_ushort(__low2half(b)), __half_as_ushort(__high2half(b))),
        pk2(__half_as_ushort(__low2half(c)), __half_as_ushort(__high2half(c))),
        pk2(__half_as_ushort(__low2half(d)), __half_as_ushort(__high2half(d))));
}

// ---------------- output: 3-stage fp16 GEMM O = E @ V' ----------------
// grid (32,8), block 128 (4 warps 2x2). C [64][64]; 16 j-chunks of 128.
__global__ __launch_bounds__(128) void out_kernel(float* __restrict__ out) {
    extern __shared__ char smem[];
    const int tid = threadIdx.x, lane = tid & 31, w = tid >> 5;
    const int it = blockIdx.x, bb = blockIdx.y;
    const int i0 = it * 64;
    const uint32_t sbase = s_u32(smem);

    const int wm = w & 1, wn = w >> 1;
    float acc[2][4][4];
    #pragma unroll
    for (int i = 0; i < 2; i++)
        #pragma unroll
        for (int j = 0; j < 4; j++)
            #pragma unroll
            for (int q = 0; q < 4; q++) acc[i][j][q] = 0.f;

    const char* Eg = (const char*)g_E;
    const char* Vg = (const char*)g_Vf;

    auto issue = [&](int c) {
        const uint32_t base = sbase + (c % 3) * 34816;
        const int j0 = c * 128;
        #pragma unroll
        for (int p = 0; p < 8; p++) {
            int lin = p * 128 + tid, r = lin >> 4, q = lin & 15;
            CPA16(base + (uint32_t)(r * 272 + q * 16),
                  Eg + ((size_t)(bb * SEQ + i0 + r) * SEQ + j0) * 2 + q * 16);
        }
        #pragma unroll
        for (int p = 0; p < 8; p++) {
            int lin = p * 128 + tid, r = lin >> 4, q = lin & 15;
            CPA16(base + 17408 + (uint32_t)(r * 272 + q * 16),
                  Vg + ((size_t)(bb * 64 + r) * SEQ + j0) * 2 + q * 16);
        }
        CPA_COMMIT();
    };

    issue(0); issue(1);
    for (int c = 0; c < 16; c++) {
        if (c + 2 < 16) { issue(c + 2); CPA_WAIT2(); }
        else if (c + 1 < 16) { CPA_WAIT1(); }
        else { CPA_WAIT0(); }
        __syncthreads();

        const uint32_t base = sbase + (c % 3) * 34816;
        const uint32_t sE = base, sV = base + 17408;
        #pragma unroll
        for (int ks = 0; ks < 8; ks++) {
            const int k0 = ks * 16;
            uint32_t a[2][4];
            #pragma unroll
            for (int mf = 0; mf < 2; mf++) {
                uint32_t off = (uint32_t)((wm * 32 + mf * 16 + (lane & 15)) * 136 +
                                          k0 + ((lane >> 4) << 3)) * 2;
                LDSM4(a[mf][0], a[mf][1], a[mf][2], a[mf][3], sE + off);
            }
            uint32_t b[4][2];
            #pragma unroll
            for (int nb = 0; nb < 2; nb++) {
                uint32_t off = (uint32_t)((wn * 32 + nb * 16 + (lane & 7) + ((lane >> 4) << 3)) * 136 +
                                          k0 + (((lane >> 3) & 1) << 3)) * 2;
                LDSM4(b[2*nb][0], b[2*nb][1], b[2*nb+1][0], b[2*nb+1][1], sV + off);
            }
            #pragma unroll
            for (int mf = 0; mf < 2; mf++)
                #pragma unroll
                for (int nf = 0; nf < 4; nf++)
                    mma_f16(acc[mf][nf], a[mf], b[nf]);
        }
        __syncthreads();
    }

    // epilogue: stage f32 (pitch 68) then coalesced store
    float* Ost = (float*)smem;
    #pragma unroll
    for (int mf = 0; mf < 2; mf++)
        #pragma unroll
        for (int nf = 0; nf < 4; nf++) {
            int col = wn * 32 + nf * 8 + (lane & 3) * 2;
            int r0 = wm * 32 + mf * 16 + (lane >> 2);
            #pragma unroll
            for (int h = 0; h < 2; h++) {
                Ost[(r0 + h * 8) * 68 + col]     = acc[mf][nf][h * 2 + 0];
                Ost[(r0 + h * 8) * 68 + col + 1] = acc[mf][nf][h * 2 + 1];
            }
        }
    __syncthreads();
    #pragma unroll
    for (int p = 0; p < 8; p++) {
        int lin = p * 128 + tid, r = lin >> 4, c4 = lin & 15;
        *(float4*)(out + ((size_t)(bb * SEQ + i0 + r)) * DH + c4 * 4) =
            *(float4*)(Ost + r * 68 + c4 * 4);
    }
}

// ---------------- launch ----------------
extern "C" void kernel_launch(void* const* d_in, const int* in_sizes, int n_in,
                              void* d_out, int out_size)
{
    const float* x  = (const float*)d_in[0];
    const float* Wq = (const float*)d_in[1];
    const float* bq = (const float*)d_in[2];
    const float* Wk = (const float*)d_in[3];
    const float* bk = (const float*)d_in[4];
    const float* Wv = (const float*)d_in[5];
    const float* bv = (const float*)d_in[6];
    float* out = (float*)d_out;

    cudaFuncSetAttribute(proj_kernel,   cudaFuncAttributeMaxDynamicSharedMemorySize, 73728);
    cudaFuncSetAttribute(scores_kernel, cudaFuncAttributeMaxDynamicSharedMemorySize, 36864);
    cudaFuncSetAttribute(out_kernel,    cudaFuncAttributeMaxDynamicSharedMemorySize, 104448);

    split_w_kernel<<<dim3(256, 3), 256>>>(Wq, Wk, Wv);   // also zeroes g_csum
    proj_kernel<<<256, 256, 73728>>>(x, bq, bk, bv);
    scores_kernel<<<dim3(16, 16, 8), 256, 36864>>>();
    scale_v_kernel<<<512, 256>>>();
    out_kernel<<<dim3(32, 8), 128, 104448>>>(out);
}

// round 16
// speedup vs baseline: 1.1450x; 1.0048x over previous
#include <cuda_runtime.h>
#include <cuda_bf16.h>
#include <cuda_fp16.h>
#include <cstdint>

#define BATCH 8
#define SEQ   2048
#define DM    1024
#define DH    64
#define NTOK  (BATCH * SEQ)
#define ITILES 16

// ---------------- device scratch ----------------
__device__ __half g_W[3 * DH * DM];                // [mat*64+c][k], fp16
__device__ __half g_Q[NTOK * DH];                  // Q fp16
__device__ __half g_K[NTOK * DH];                  // K fp16
__device__ __half g_E[(size_t)NTOK * SEQ];         // exp(S) fp16, [b,i,j]
__device__ __half g_Vf[BATCH * DH * SEQ];          // V fp16 UNSCALED, [b][d][i]
__device__ float  g_csum[BATCH * SEQ];             // atomic column sums

// ---------------- helpers ----------------
__device__ __forceinline__ uint32_t s_u32(const void* p) {
    uint32_t a;
    asm("{ .reg .u64 t; cvta.to.shared.u64 t, %1; cvt.u32.u64 %0, t; }" : "=r"(a) : "l"(p));
    return a;
}
#define LDSM4(r0, r1, r2, r3, addr) \
    asm volatile("ldmatrix.sync.aligned.m8n8.x4.shared.b16 {%0,%1,%2,%3}, [%4];" \
                 : "=r"(r0), "=r"(r1), "=r"(r2), "=r"(r3) : "r"(addr))
#define CPA16(dst, src) \
    asm volatile("cp.async.cg.shared.global [%0], [%1], 16;" :: "r"(dst), "l"(src))
#define CPA_COMMIT() asm volatile("cp.async.commit_group;" ::: "memory")
#define CPA_WAIT2()  asm volatile("cp.async.wait_group 2;" ::: "memory")
#define CPA_WAIT1()  asm volatile("cp.async.wait_group 1;" ::: "memory")
#define CPA_WAIT0()  asm volatile("cp.async.wait_group 0;" ::: "memory")

__device__ __forceinline__ void mma_f16(float* c, const uint32_t* a, const uint32_t* b) {
    asm volatile(
        "mma.sync.aligned.m16n8k16.row.col.f32.f16.f16.f32 "
        "{%0,%1,%2,%3}, {%4,%5,%6,%7}, {%8,%9}, {%0,%1,%2,%3};"
        : "+f"(c[0]), "+f"(c[1]), "+f"(c[2]), "+f"(c[3])
        : "r"(a[0]), "r"(a[1]), "r"(a[2]), "r"(a[3]), "r"(b[0]), "r"(b[1]));
}
__device__ __forceinline__ uint32_t pk2(unsigned short a, unsigned short b) {
    return (uint32_t)a | ((uint32_t)b << 16);
}
__device__ __forceinline__ unsigned short h16(float v) {
    return __half_as_ushort(__float2half(v));
}

// ---------------- W -> fp16 transpose (+ zero g_csum) ----------------
__global__ __launch_bounds__(256) void split_w_kernel(
    const float* __restrict__ Wq, const float* __restrict__ Wk, const float* __restrict__ Wv) {
    int mt = blockIdx.y;
    const float* W = (mt == 0) ? Wq : (mt == 1) ? Wk : Wv;
    int idx = blockIdx.x * 256 + threadIdx.x;
    int k = idx >> 6, c = idx & 63;
    g_W[(mt * 64 + c) * DM + k] = __float2half(W[k * DH + c]);
    if (mt == 0 && idx < BATCH * SEQ) g_csum[idx] = 0.f;
}

// ---------------- fused QKV projection: 64-row tiles, 256 CTAs ----------------
// grid 256, block 256 (8 warps 2x4). Stage (36864 B x2): A[64][72] @0 (9216), B[192][72] @9216 (27648)
__global__ __launch_bounds__(256) void proj_kernel(
    const float* __restrict__ x, const float* __restrict__ bq,
    const float* __restrict__ bk, const float* __restrict__ bv) {
    extern __shared__ char smem[];
    const uint32_t sbase = s_u32(smem);
    const int tid = threadIdx.x, lane = tid & 31, w = tid >> 5;
    const int row0 = blockIdx.x * 64;
    const int bb = row0 >> 11, iloc = row0 & 2047;

    const int wm = w & 1, wn = w >> 1;          // rows wm*32, cols wn*48
    float acc[2][6][4];
    #pragma unroll
    for (int i = 0; i < 2; i++)
        #pragma unroll
        for (int j = 0; j < 6; j++)
            #pragma unroll
            for (int q = 0; q < 4; q++) acc[i][j][q] = 0.f;

    const int xr_r = tid >> 2, xr_c = (tid & 3) * 16;

    auto ldx = [&](int kc, float4* xr) {
        const float4* src = (const float4*)(x + (size_t)(row0 + xr_r) * DM + kc * 64 + xr_c);
        xr[0] = src[0]; xr[1] = src[1]; xr[2] = src[2]; xr[3] = src[3];
    };
    auto convA = [&](const float4* xr, int st) {
        __half* A = (__half*)(smem + st * 36864);
        unsigned short hs[16];
        #pragma unroll
        for (int q = 0; q < 4; q++) {
            float4 v = xr[q];
            hs[q*4+0] = h16(v.x); hs[q*4+1] = h16(v.y);
            hs[q*4+2] = h16(v.z); hs[q*4+3] = h16(v.w);
        }
        uint4* dh = (uint4*)(A + xr_r * 72 + xr_c);
        dh[0] = make_uint4(pk2(hs[0],hs[1]), pk2(hs[2],hs[3]), pk2(hs[4],hs[5]), pk2(hs[6],hs[7]));
        dh[1] = make_uint4(pk2(hs[8],hs[9]), pk2(hs[10],hs[11]), pk2(hs[12],hs[13]), pk2(hs[14],hs[15]));
    };
    auto ldW = [&](int kc, int st) {
        uint32_t bw = sbase + st * 36864 + 9216;
        #pragma unroll
        for (int p = 0; p < 6; p++) {
            int lin = p * 256 + tid, r = lin >> 3, q = lin & 7;
            CPA16(bw + (uint32_t)(r * 144 + q * 16),
                  (const char*)g_W + ((size_t)r * DM + kc * 64) * 2 + q * 16);
        }
        CPA_COMMIT();
    };

    float4 xr[4];
    ldx(0, xr);
    ldW(0, 0);
    convA(xr, 0);
    CPA_WAIT0();
    __syncthreads();

    for (int c = 0; c < 16; c++) {
        const int cur = c & 1;
        if (c < 15) { ldx(c + 1, xr); ldW(c + 1, cur ^ 1); }

        const uint32_t S = sbase + cur * 36864;
        const uint32_t sA = S, sB = S + 9216;
        #pragma unroll
        for (int ks = 0; ks < 4; ks++) {
            const int k0 = ks * 16;
            uint32_t a[2][4];
            #pragma unroll
            for (int mf = 0; mf < 2; mf++) {
                uint32_t off = (uint32_t)((wm * 32 + mf * 16 + (lane & 15)) * 72 +
                                          k0 + ((lane >> 4) << 3)) * 2;
                LDSM4(a[mf][0], a[mf][1], a[mf][2], a[mf][3], sA + off);
            }
            uint32_t b[6][2];
            #pragma unroll
            for (int nb = 0; nb < 3; nb++) {
                uint32_t off = (uint32_t)((wn * 48 + nb * 16 + (lane & 7) + ((lane >> 4) << 3)) * 72 +
                                          k0 + (((lane >> 3) & 1) << 3)) * 2;
                LDSM4(b[2*nb][0], b[2*nb][1], b[2*nb+1][0], b[2*nb+1][1], sB + off);
            }
            #pragma unroll
            for (int mf = 0; mf < 2; mf++)
                #pragma unroll
                for (int nf = 0; nf < 6; nf++)
                    mma_f16(acc[mf][nf], a[mf], b[nf]);
        }
        if (c < 15) { convA(xr, cur ^ 1); CPA_WAIT0(); }
        __syncthreads();
    }

    // epilogue: Q, K fp16 direct; V staged fp16 transposed ([64 d][80] pitch)
    __half* sVh = (__half*)smem;   // 64*80*2 = 10240 B
    #pragma unroll
    for (int mf = 0; mf < 2; mf++)
        #pragma unroll
        for (int nf = 0; nf < 6; nf++) {
            int gc = wn * 48 + nf * 8 + (lane & 3) * 2;
            int mt = gc >> 6, cm = gc & 63;
            int r0 = wm * 32 + mf * 16 + (lane >> 2);
            #pragma unroll
            for (int h = 0; h < 2; h++) {
                int rl = r0 + h * 8;
                float v0 = acc[mf][nf][h * 2 + 0], v1 = acc[mf][nf][h * 2 + 1];
                if (mt == 0) {
                    size_t o = (size_t)(row0 + rl) * DH + cm;
                    *(uint32_t*)(g_Q + o) = pk2(h16(v0 + bq[cm]), h16(v1 + bq[cm + 1]));
                } else if (mt == 1) {
                    size_t o = (size_t)(row0 + rl) * DH + cm;
                    *(uint32_t*)(g_K + o) = pk2(h16(v0 + bk[cm]), h16(v1 + bk[cm + 1]));
                } else {
                    sVh[cm * 80 + rl]       = __ushort_as_half(h16(v0 + bv[cm]));
                    sVh[(cm + 1) * 80 + rl] = __ushort_as_half(h16(v1 + bv[cm + 1]));
                }
            }
        }
    __syncthreads();
    // transposed V store: 64 d-rows x 64 i halves = 512 uint4
    #pragma unroll
    for (int p = 0; p < 2; p++) {
        int lin = p * 256 + tid, r = lin >> 3, q = lin & 7;
        *(uint4*)((char*)g_Vf + ((size_t)(bb * 64 + r) * SEQ + iloc) * 2 + q * 16) =
            *(uint4*)((char*)sVh + r * 160 + q * 16);
    }
}

// ---------------- scores -> E = exp(S) (fp16) + atomic column sums ----------------
// grid (16,16,8), block 256. smem: Q,K [128][72]h (36864 B); reused as Est fp16 pitch 136.
__global__ __launch_bounds__(256) void scores_kernel() {
    extern __shared__ char smem[];
    __shared__ float sred[256];
    const int tid = threadIdx.x, lane = tid & 31, w = tid >> 5;
    const int jt = blockIdx.x, it = blockIdx.y, bb = blockIdx.z;
    const int i0 = it * 128, j0 = jt * 128;
    const uint32_t sbase = s_u32(smem);

    {
        const __half* src[2] = { g_Q, g_K };
        #pragma unroll
        for (int a = 0; a < 2; a++) {
            const int rb = bb * SEQ + ((a == 0) ? i0 : j0);
            #pragma unroll
            for (int p = 0; p < 4; p++) {
                int lin = p * 256 + tid, r = lin >> 3, q = lin & 7;
                CPA16(sbase + a * 18432 + (uint32_t)(r * 144 + q * 16),
                      (const char*)src[a] + ((size_t)(rb + r) * DH) * 2 + q * 16);
            }
        }
        CPA_COMMIT(); CPA_WAIT0();
    }
    __syncthreads();

    const uint32_t sQ = sbase, sK = sbase + 18432;
    const int wm = w & 1, wn = w >> 1;          // rows wm*64, cols wn*32
    float acc[4][4][4];
    #pragma unroll
    for (int i = 0; i < 4; i++)
        #pragma unroll
        for (int j = 0; j < 4; j++)
            #pragma unroll
            for (int q = 0; q < 4; q++) acc[i][j][q] = 0.f;

    #pragma unroll
    for (int ks = 0; ks < 4; ks++) {
        const int k0 = ks * 16;
        uint32_t a[4][4];
        #pragma unroll
        for (int mf = 0; mf < 4; mf++) {
            uint32_t off = (uint32_t)((wm * 64 + mf * 16 + (lane & 15)) * 72 +
                                      k0 + ((lane >> 4) << 3)) * 2;
            LDSM4(a[mf][0], a[mf][1], a[mf][2], a[mf][3], sQ + off);
        }
        uint32_t b[4][2];
        #pragma unroll
        for (int nb = 0; nb < 2; nb++) {
            uint32_t off = (uint32_t)((wn * 32 + nb * 16 + (lane & 7) + ((lane >> 4) << 3)) * 72 +
                                      k0 + (((lane >> 3) & 1) << 3)) * 2;
            LDSM4(b[2*nb][0], b[2*nb][1], b[2*nb+1][0], b[2*nb+1][1], sK + off);
        }
        #pragma unroll
        for (int mf = 0; mf < 4; mf++)
            #pragma unroll
            for (int nf = 0; nf < 4; nf++)
                mma_f16(acc[mf][nf], a[mf], b[nf]);
    }
    __syncthreads();

    // stage E = exp(S/8) as fp16 (pitch 136 halves)
    __half* Est = (__half*)smem;
    #pragma unroll
    for (int mf = 0; mf < 4; mf++)
        #pragma unroll
        for (int nf = 0; nf < 4; nf++) {
            int col = wn * 32 + nf * 8 + (lane & 3) * 2;
            int r0 = wm * 64 + mf * 16 + (lane >> 2);
            #pragma unroll
            for (int h = 0; h < 2; h++) {
                float e0 = __expf(0.125f * acc[mf][nf][h * 2 + 0]);
                float e1 = __expf(0.125f * acc[mf][nf][h * 2 + 1]);
                *(__half2*)(Est + (r0 + h * 8) * 136 + col) = __floats2half2_rn(e0, e1);
            }
        }
    __syncthreads();
    // coalesced fp16 E store
    #pragma unroll
    for (int p = 0; p < 8; p++) {
        int lin = p * 256 + tid, r = lin >> 4, c8 = lin & 15;
        *(uint4*)((char*)g_E + ((size_t)(bb * SEQ + i0 + r) * SEQ + j0) * 2 + c8 * 16) =
            *(uint4*)((char*)Est + r * 272 + c8 * 16);
    }
    // per-column partial sums (2-way row split) + atomic accumulate
    {
        int col = tid & 127, hf = tid >> 7;
        float s = 0.f;
        #pragma unroll 8
        for (int i = 0; i < 64; i++) s += __half2float(Est[(hf * 64 + i) * 136 + col]);
        sred[tid] = s;
        __syncthreads();
        if (tid < 128)
            atomicAdd(&g_csum[bb * SEQ + j0 + tid], sred[tid] + sred[tid + 128]);
    }
}

// ---------------- output: 3-stage fp16 GEMM O = E @ (c*V), c applied in smem ----------------
// grid (32,8), block 128 (4 warps 2x2). C [64][64]; 16 j-chunks of 128.
// smem: 3 stages x 34816 (E 17408 + V 17408) + inv-csum table 4096 = 108544
__global__ __launch_bounds__(128) void out_kernel(float* __restrict__ out) {
    extern __shared__ char smem[];
    const int tid = threadIdx.x, lane = tid & 31, w = tid >> 5;
    const int it = blockIdx.x, bb = blockIdx.y;
    const int i0 = it * 64;
    const uint32_t sbase = s_u32(smem);
    __half* ch = (__half*)(smem + 104448);   // 2048 inverse column sums

    const int wm = w & 1, wn = w >> 1;
    float acc[2][4][4];
    #pragma unroll
    for (int i = 0; i < 2; i++)
        #pragma unroll
        for (int j = 0; j < 4; j++)
            #pragma unroll
            for (int q = 0; q < 4; q++) acc[i][j][q] = 0.f;

    const char* Eg = (const char*)g_E;
    const char* Vg = (const char*)g_Vf;

    auto issue = [&](int c) {
        const uint32_t base = sbase + (c % 3) * 34816;
        const int j0 = c * 128;
        #pragma unroll
        for (int p = 0; p < 8; p++) {
            int lin = p * 128 + tid, r = lin >> 4, q = lin & 15;
            CPA16(base + (uint32_t)(r * 272 + q * 16),
                  Eg + ((size_t)(bb * SEQ + i0 + r) * SEQ + j0) * 2 + q * 16);
        }
        #pragma unroll
        for (int p = 0; p < 8; p++) {
            int lin = p * 128 + tid, r = lin >> 4, q = lin & 15;
            CPA16(base + 17408 + (uint32_t)(r * 272 + q * 16),
                  Vg + ((size_t)(bb * 64 + r) * SEQ + j0) * 2 + q * 16);
        }
        CPA_COMMIT();
    };

    issue(0); issue(1);
    // build inverse-csum table (LDG latency overlaps the cp.asyncs above)
    #pragma unroll
    for (int p = 0; p < 16; p++) {
        int j = p * 128 + tid;
        ch[j] = __float2half(__fdividef(1.0f, g_csum[bb * SEQ + j]));
    }

    for (int c = 0; c < 16; c++) {
        if (c + 2 < 16) { issue(c + 2); CPA_WAIT2(); }
        else if (c + 1 < 16) { CPA_WAIT1(); }
        else { CPA_WAIT0(); }
        __syncthreads();   // also publishes ch on first iteration

        const uint32_t base = sbase + (c % 3) * 34816;
        // scale V tile in place: V[d][j] *= ch[j0 + j]
        {
            const __half2* cp2 = (const __half2*)(ch + c * 128 + (tid & 15) * 8);
            __half2 c0 = cp2[0], c1 = cp2[1], c2 = cp2[2], c3 = cp2[3];
            char* vb = smem + (c % 3) * 34816 + 17408;
            int g = tid & 15, rb = tid >> 4;
            #pragma unroll
            for (int p = 0; p < 8; p++) {
                uint4* vp = (uint4*)(vb + (rb + p * 8) * 272 + g * 16);
                uint4 v = *vp;
                __half2 h0 = __hmul2(*(__half2*)&v.x, c0);
                __half2 h1 = __hmul2(*(__half2*)&v.y, c1);
                __half2 h2 = __hmul2(*(__half2*)&v.z, c2);
                __half2 h3 = __hmul2(*(__half2*)&v.w, c3);
                v.x = *(uint32_t*)&h0; v.y = *(uint32_t*)&h1;
                v.z = *(uint32_t*)&h2; v.w = *(uint32_t*)&h3;
                *vp = v;
            }
        }
        __syncthreads();

        const uint32_t sE = base, sV = base + 17408;
        #pragma unroll
        for (int ks = 0; ks < 8; ks++) {
            const int k0 = ks * 16;
            uint32_t a[2][4];
            #pragma unroll
            for (int mf = 0; mf < 2; mf++) {
                uint32_t off = (uint32_t)((wm * 32 + mf * 16 + (lane & 15)) * 136 +
                                          k0 + ((lane >> 4) << 3)) * 2;
                LDSM4(a[mf][0], a[mf][1], a[mf][2], a[mf][3], sE + off);
            }
            uint32_t b[4][2];
            #pragma unroll
            for (int nb = 0; nb < 2; nb++) {
                uint32_t off = (uint32_t)((wn * 32 + nb * 16 + (lane & 7) + ((lane >> 4) << 3)) * 136 +
                                          k0 + (((lane >> 3) & 1) << 3)) * 2;
                LDSM4(b[2*nb][0], b[2*nb][1], b[2*nb+1][0], b[2*nb+1][1], sV + off);
            }
            #pragma unroll
            for (int mf = 0; mf < 2; mf++)
                #pragma unroll
                for (int nf = 0; nf < 4; nf++)
                    mma_f16(acc[mf][nf], a[mf], b[nf]);
        }
        __syncthreads();
    }

    // epilogue: stage f32 (pitch 68) then coalesced store
    float* Ost = (float*)smem;
    #pragma unroll
    for (int mf = 0; mf < 2; mf++)
        #pragma unroll
        for (int nf = 0; nf < 4; nf++) {
            int col = wn * 32 + nf * 8 + (lane & 3) * 2;
            int r0 = wm * 32 + mf * 16 + (lane >> 2);
            #pragma unroll
            for (int h = 0; h < 2; h++) {
                Ost[(r0 + h * 8) * 68 + col]     = acc[mf][nf][h * 2 + 0];
                Ost[(r0 + h * 8) * 68 + col + 1] = acc[mf][nf][h * 2 + 1];
            }
        }
    __syncthreads();
    #pragma unroll
    for (int p = 0; p < 8; p++) {
        int lin = p * 128 + tid, r = lin >> 4, c4 = lin & 15;
        *(float4*)(out + ((size_t)(bb * SEQ + i0 + r)) * DH + c4 * 4) =
            *(float4*)(Ost + r * 68 + c4 * 4);
    }
}

// ---------------- launch ----------------
extern "C" void kernel_launch(void* const* d_in, const int* in_sizes, int n_in,
                              void* d_out, int out_size)
{
    const float* x  = (const float*)d_in[0];
    const float* Wq = (const float*)d_in[1];
    const float* bq = (const float*)d_in[2];
    const float* Wk = (const float*)d_in[3];
    const float* bk = (const float*)d_in[4];
    const float* Wv = (const float*)d_in[5];
    const float* bv = (const float*)d_in[6];
    float* out = (float*)d_out;

    cudaFuncSetAttribute(proj_kernel,   cudaFuncAttributeMaxDynamicSharedMemorySize, 73728);
    cudaFuncSetAttribute(scores_kernel, cudaFuncAttributeMaxDynamicSharedMemorySize, 36864);
    cudaFuncSetAttribute(out_kernel,    cudaFuncAttributeMaxDynamicSharedMemorySize, 108544);

    split_w_kernel<<<dim3(256, 3), 256>>>(Wq, Wk, Wv);   // also zeroes g_csum
    proj_kernel<<<256, 256, 73728>>>(x, bq, bk, bv);
    scores_kernel<<<dim3(16, 16, 8), 256, 36864>>>();
    out_kernel<<<dim3(32, 8), 128, 108544>>>(out);
}